// round 14
// baseline (speedup 1.0000x reference)
#include <cuda_runtime.h>
#include <cuda_fp16.h>
#include <math.h>
#include <cstdint>

#define HID    2304
#define HALF_D 1152
#define NHEADS 16
#define NH17   17
#define DH     144
#define SLEN   2048
#define MMAX   8192

// -------- scratch (static device globals; no runtime allocation) ----------
__device__ __half g_q16[(size_t)MMAX * HID];
__device__ __half g_k16[(size_t)MMAX * HID];
__device__ __half g_v16[(size_t)MMAX * HID];
__device__ float  g_o[(size_t)MMAX * HID];
__device__ __half g_xh[(size_t)MMAX * HID];
__device__ __half g_attnh[(size_t)MMAX * HID];
__device__ __half g_wqkvh[(size_t)3 * HID * HID];   // packed [3*HID, HID]
__device__ __half g_woh[(size_t)HID * HID];
__device__ float  g_cos[SLEN * HALF_D];
__device__ float  g_sin[SLEN * HALF_D];
__device__ double g_omega[HALF_D];

// ---------------------------------------------------------------------------
// RoPE tables.
// ---------------------------------------------------------------------------
__global__ void build_omega_kernel() {
    int i = blockIdx.x * blockDim.x + threadIdx.x;
    if (i < HALF_D) {
        double scale = (2.0 * (double)i) / (double)HID;
        g_omega[i] = exp(-scale * log(10000.0));
    }
}

__global__ void build_rope_kernel() {
    int idx = blockIdx.x * blockDim.x + threadIdx.x;
    if (idx >= SLEN * HALF_D) return;
    int pos = idx / HALF_D;
    int i   = idx - pos * HALF_D;
    double ang = (double)pos * g_omega[i];
    double n = floor(ang * 0.15915494309189535);
    double r = ang - n * 6.283185307179586476925286766559;
    float s, c;
    sincosf((float)r, &s, &c);
    g_cos[idx] = c;
    g_sin[idx] = s;
}

// ---------------------------------------------------------------------------
// One-shot conversion, direct-indexed (one float4 per thread, one branch).
// ---------------------------------------------------------------------------
__global__ void convert_all_kernel(const float* __restrict__ x,
                                   const float* __restrict__ wq,
                                   const float* __restrict__ wk,
                                   const float* __restrict__ wv,
                                   const float* __restrict__ wo,
                                   __half* __restrict__ xh,
                                   __half* __restrict__ wqkvh,
                                   __half* __restrict__ woh,
                                   int nx4, int nw4) {
    int i = blockIdx.x * blockDim.x + threadIdx.x;
    int total = nx4 + 4 * nw4;
    if (i >= total) return;
    const float* src;
    __half* dst;
    int idx;
    if (i < nx4) {
        src = x; dst = xh; idx = i;
    } else {
        int j = i - nx4;
        int w = j / nw4;       // 0..3
        idx = j - w * nw4;
        src = (w == 0) ? wq : (w == 1) ? wk : (w == 2) ? wv : wo;
        dst = (w == 0) ? wqkvh
            : (w == 1) ? wqkvh + (size_t)HID * HID
            : (w == 2) ? wqkvh + (size_t)2 * HID * HID
            : woh;
    }
    float4 v = ((const float4*)src)[idx];
    ((__half2*)dst)[2 * idx]     = __floats2half2_rn(v.x, v.y);
    ((__half2*)dst)[2 * idx + 1] = __floats2half2_rn(v.z, v.w);
}

// ---------------------------------------------------------------------------
// PTX helpers
// ---------------------------------------------------------------------------
__device__ __forceinline__ void cp_async16(uint32_t dst, const void* src) {
    asm volatile("cp.async.cg.shared.global [%0], [%1], 16;\n" :: "r"(dst), "l"(src));
}
__device__ __forceinline__ void cp_commit() {
    asm volatile("cp.async.commit_group;\n");
}
__device__ __forceinline__ void cp_wait1() {
    asm volatile("cp.async.wait_group 1;\n");
}

#define LDSM4(r0, r1, r2, r3, addr) \
    asm volatile("ldmatrix.sync.aligned.m8n8.x4.shared.b16 {%0,%1,%2,%3}, [%4];" \
                 : "=r"(r0), "=r"(r1), "=r"(r2), "=r"(r3) : "r"(addr))

#define MMA_F16(d, a0, a1, a2, a3, b0, b1) \
    asm volatile("mma.sync.aligned.m16n8k16.row.col.f32.f16.f16.f32 " \
                 "{%0,%1,%2,%3}, {%4,%5,%6,%7}, {%8,%9}, {%0,%1,%2,%3};" \
                 : "+f"((d)[0]), "+f"((d)[1]), "+f"((d)[2]), "+f"((d)[3]) \
                 : "r"(a0), "r"(a1), "r"(a2), "r"(a3), "r"(b0), "r"(b1))

// ---------------------------------------------------------------------------
// GEMM core: CTA tile 128x128, 128 threads (4 warps, 64x64), 2 CTAs/SM,
// 3-stage cp.async pipeline + LDSM double-buffer + interleaved cp.async.
// ---------------------------------------------------------------------------
#define BM 128
#define BN 128
#define BKH 64                              // K halfs per stage (128 bytes)
#define A_BYTES (BM * 128)
#define B_BYTES (BN * 128)
#define STAGE_BYTES (A_BYTES + B_BYTES)     // 32768
#define GEMM_SMEM_BYTES (3 * STAGE_BYTES)   // 98304 per CTA

__device__ __forceinline__ void load_stage_A(const __half* __restrict__ A,
                                             int K, int bm, int k0,
                                             uint32_t stg, int tid) {
    #pragma unroll
    for (int i = 0; i < 8; i++) {
        int e = i * 128 + tid;
        int r = e >> 3;
        int cb = (e & 7) * 16;
        cp_async16(stg + r * 128 + (cb ^ ((r & 7) << 4)),
                   A + (size_t)(bm + r) * K + k0 + (e & 7) * 8);
    }
}
__device__ __forceinline__ void load_stage_B(const __half* __restrict__ B,
                                             int K, int bn, int k0,
                                             uint32_t stg, int tid) {
    #pragma unroll
    for (int i = 0; i < 8; i++) {
        int e = i * 128 + tid;
        int r = e >> 3;
        int cb = (e & 7) * 16;
        cp_async16(stg + A_BYTES + r * 128 + (cb ^ ((r & 7) << 4)),
                   B + (size_t)(bn + r) * K + k0 + (e & 7) * 8);
    }
}

struct Frag { uint32_t a[4][4]; uint32_t b[4][4]; };

__device__ __forceinline__ void ldsm_all(Frag& f, uint32_t stg, int kk,
                                         const int* rowA, const int* rowB,
                                         int lh, int lc) {
    const int kbL = kk * 32;
    #pragma unroll
    for (int mb = 0; mb < 4; mb++) {
        uint32_t ad = stg + rowA[mb] * 128 +
                      ((kbL + lc * 16) ^ ((rowA[mb] & 7) << 4));
        LDSM4(f.a[mb][0], f.a[mb][1], f.a[mb][2], f.a[mb][3], ad);
    }
    #pragma unroll
    for (int j = 0; j < 4; j++) {
        uint32_t bd = stg + A_BYTES + rowB[j] * 128 +
                      ((kbL + lh * 16) ^ ((rowB[j] & 7) << 4));
        LDSM4(f.b[j][0], f.b[j][1], f.b[j][2], f.b[j][3], bd);
    }
}

__device__ __forceinline__ void mma_all(float acc[4][8][4], const Frag& f) {
    #pragma unroll
    for (int mb = 0; mb < 4; mb++)
        #pragma unroll
        for (int j = 0; j < 4; j++) {
            MMA_F16(acc[mb][2 * j],     f.a[mb][0], f.a[mb][1], f.a[mb][2], f.a[mb][3],
                    f.b[j][0], f.b[j][1]);
            MMA_F16(acc[mb][2 * j + 1], f.a[mb][0], f.a[mb][1], f.a[mb][2], f.a[mb][3],
                    f.b[j][2], f.b[j][3]);
        }
}

__device__ __forceinline__ void gemm_mainloop(const __half* A, const __half* B,
                                              int K, int bm, int bn,
                                              uint32_t sbase, int tid,
                                              const int* rowA, const int* rowB,
                                              int lh, int lc,
                                              float acc[4][8][4]) {
    const int kIters = K / BKH;   // 36

    load_stage_A(A, K, bm, 0, sbase, tid);
    load_stage_B(B, K, bn, 0, sbase, tid);
    cp_commit();
    load_stage_A(A, K, bm, BKH, sbase + STAGE_BYTES, tid);
    load_stage_B(B, K, bn, BKH, sbase + STAGE_BYTES, tid);
    cp_commit();

    int stage = 0;
    for (int kt = 0; kt < kIters; kt++) {
        cp_wait1();
        __syncthreads();

        const uint32_t stg = sbase + stage * STAGE_BYTES;
        const int nk = kt + 2;
        const bool pf = nk < kIters;
        const uint32_t nstg = sbase + (nk % 3) * STAGE_BYTES;

        Frag f[2];
        ldsm_all(f[0], stg, 0, rowA, rowB, lh, lc);
        ldsm_all(f[1], stg, 1, rowA, rowB, lh, lc);

        if (pf) load_stage_A(A, K, bm, nk * BKH, nstg, tid);
        mma_all(acc, f[0]);
        ldsm_all(f[0], stg, 2, rowA, rowB, lh, lc);

        if (pf) load_stage_B(B, K, bn, nk * BKH, nstg, tid);
        mma_all(acc, f[1]);
        ldsm_all(f[1], stg, 3, rowA, rowB, lh, lc);
        cp_commit();

        mma_all(acc, f[0]);
        mma_all(acc, f[1]);

        stage = (stage + 1 == 3) ? 0 : stage + 1;
    }
}

// ---------------------------------------------------------------------------
// Fused q/k/v projection: B packed [3*HID, HID]; per-CTA sel picks output.
// ---------------------------------------------------------------------------
__global__ __launch_bounds__(128, 2)
void gemm_qkv_kernel(const __half* __restrict__ A, const __half* __restrict__ B,
                     const float* __restrict__ bq, const float* __restrict__ bk,
                     const float* __restrict__ bv, int M, int K) {
    extern __shared__ char smem[];
    uint32_t sbase;
    asm("{ .reg .u64 t; cvta.to.shared.u64 t, %1; cvt.u32.u64 %0, t; }"
        : "=r"(sbase) : "l"(smem));

    const int tid  = threadIdx.x;
    const int warp = tid >> 5;
    const int lane = tid & 31;
    const int bm = blockIdx.y * BM;
    const int bn = blockIdx.x * BN;
    const int wm = (warp >> 1) * 64;
    const int wn = (warp & 1) * 64;

    const int lr = lane & 7;
    const int lh = (lane >> 3) & 1;
    const int lc = lane >> 4;

    int rowA[4], rowB[4];
    #pragma unroll
    for (int mb = 0; mb < 4; mb++) rowA[mb] = wm + mb * 16 + lr + lh * 8;
    #pragma unroll
    for (int j = 0; j < 4; j++)    rowB[j] = wn + j * 16 + lr + lc * 8;

    float acc[4][8][4];
    #pragma unroll
    for (int mb = 0; mb < 4; mb++)
        #pragma unroll
        for (int nb = 0; nb < 8; nb++)
            #pragma unroll
            for (int e = 0; e < 4; e++) acc[mb][nb][e] = 0.0f;

    gemm_mainloop(A, B, K, bm, bn, sbase, tid, rowA, rowB, lh, lc, acc);

    // ---- epilogue: per-CTA uniform output selection ----
    const int sel   = bn / HID;              // 0=q, 1=k, 2=v
    const int cbase = bn - sel * HID;
    const float* bias = (sel == 0) ? bq : (sel == 1) ? bk : bv;
    __half* Ch = (sel == 0) ? g_q16 : (sel == 1) ? g_k16 : g_v16;

    #pragma unroll
    for (int mb = 0; mb < 4; mb++) {
        const int r0 = bm + wm + mb * 16 + (lane >> 2);
        #pragma unroll
        for (int nb = 0; nb < 8; nb++) {
            const int lcol = cbase + wn + nb * 8 + (lane & 3) * 2;
            float x0 = acc[mb][nb][0], x1 = acc[mb][nb][1];
            float y0 = acc[mb][nb][2], y1 = acc[mb][nb][3];
            float2 bb = *(const float2*)(bias + lcol);
            x0 += bb.x; x1 += bb.y;
            y0 += bb.x; y1 += bb.y;
            if (sel < 2) {   // RoPE for q, k
                const int i = lcol >> 1;
                const int p0 = r0 & (SLEN - 1);
                const int p1 = (r0 + 8) & (SLEN - 1);
                float c0 = g_cos[p0 * HALF_D + i], s0 = g_sin[p0 * HALF_D + i];
                float c1 = g_cos[p1 * HALF_D + i], s1 = g_sin[p1 * HALF_D + i];
                float t0 = c0 * x0 - s0 * x1;
                float t1 = s0 * x0 + c0 * x1;
                x0 = t0; x1 = t1;
                t0 = c1 * y0 - s1 * y1;
                t1 = s1 * y0 + c1 * y1;
                y0 = t0; y1 = t1;
            }
            *(__half2*)(Ch + (size_t)r0 * HID + lcol)       = __floats2half2_rn(x0, x1);
            *(__half2*)(Ch + (size_t)(r0 + 8) * HID + lcol) = __floats2half2_rn(y0, y1);
        }
    }
}

// ---------------------------------------------------------------------------
// Output projection GEMM: plain f32 store.
// ---------------------------------------------------------------------------
__global__ __launch_bounds__(128, 2)
void gemm_wo_kernel(const __half* __restrict__ A, const __half* __restrict__ B,
                    float* __restrict__ C, int M, int N, int K) {
    extern __shared__ char smem[];
    uint32_t sbase;
    asm("{ .reg .u64 t; cvta.to.shared.u64 t, %1; cvt.u32.u64 %0, t; }"
        : "=r"(sbase) : "l"(smem));

    const int tid  = threadIdx.x;
    const int warp = tid >> 5;
    const int lane = tid & 31;
    const int bm = blockIdx.y * BM;
    const int bn = blockIdx.x * BN;
    const int wm = (warp >> 1) * 64;
    const int wn = (warp & 1) * 64;

    const int lr = lane & 7;
    const int lh = (lane >> 3) & 1;
    const int lc = lane >> 4;

    int rowA[4], rowB[4];
    #pragma unroll
    for (int mb = 0; mb < 4; mb++) rowA[mb] = wm + mb * 16 + lr + lh * 8;
    #pragma unroll
    for (int j = 0; j < 4; j++)    rowB[j] = wn + j * 16 + lr + lc * 8;

    float acc[4][8][4];
    #pragma unroll
    for (int mb = 0; mb < 4; mb++)
        #pragma unroll
        for (int nb = 0; nb < 8; nb++)
            #pragma unroll
            for (int e = 0; e < 4; e++) acc[mb][nb][e] = 0.0f;

    gemm_mainloop(A, B, K, bm, bn, sbase, tid, rowA, rowB, lh, lc, acc);

    #pragma unroll
    for (int mb = 0; mb < 4; mb++) {
        const int r0 = bm + wm + mb * 16 + (lane >> 2);
        #pragma unroll
        for (int nb = 0; nb < 8; nb++) {
            const int gc = bn + wn + nb * 8 + (lane & 3) * 2;
            *(float2*)(C + (size_t)r0 * N + gc) =
                make_float2(acc[mb][nb][0], acc[mb][nb][1]);
            *(float2*)(C + (size_t)(r0 + 8) * N + gc) =
                make_float2(acc[mb][nb][2], acc[mb][nb][3]);
        }
    }
}

// ======================= head-mixing attention =============================
__global__ __launch_bounds__(256)
void attention_kernel(int M) {
    __shared__ float qt[DH * NH17];
    __shared__ float kt[DH * NH17];
    __shared__ float vs[HID];
    __shared__ float w[NHEADS * NHEADS];

    int p = blockIdx.x;
    int t = threadIdx.x;
    const __half2* qrow = (const __half2*)(g_q16 + (size_t)p * HID);
    const __half2* krow = (const __half2*)(g_k16 + (size_t)p * HID);
    const __half2* vrow = (const __half2*)(g_v16 + (size_t)p * HID);

    for (int c2 = t; c2 < HID / 2; c2 += 256) {
        int c = 2 * c2;
        int n = c / DH;
        int j = c - n * DH;
        float2 qf = __half22float2(qrow[c2]);
        float2 kf = __half22float2(krow[c2]);
        float2 vf = __half22float2(vrow[c2]);
        qt[j * NH17 + n] = qf.x;
        qt[(j + 1) * NH17 + n] = qf.y;
        kt[j * NH17 + n] = kf.x;
        kt[(j + 1) * NH17 + n] = kf.y;
        vs[c] = vf.x;
        vs[c + 1] = vf.y;
    }
    __syncthreads();

    {
        int m = t >> 4;
        int n = t & 15;
        float acc = 0.0f;
        #pragma unroll 8
        for (int j = 0; j < DH; j++)
            acc += qt[j * NH17 + n] * kt[j * NH17 + m];
        w[n * NHEADS + m] = acc * (1.0f / 12.0f);
    }
    __syncthreads();

    if (t < NHEADS) {
        float mx = -1e30f;
        #pragma unroll
        for (int m = 0; m < NHEADS; m++) mx = fmaxf(mx, w[t * NHEADS + m]);
        float sum = 0.0f;
        #pragma unroll
        for (int m = 0; m < NHEADS; m++) {
            float e = expf(w[t * NHEADS + m] - mx);
            w[t * NHEADS + m] = e;
            sum += e;
        }
        float inv = 1.0f / sum;
        #pragma unroll
        for (int m = 0; m < NHEADS; m++) w[t * NHEADS + m] *= inv;
    }
    __syncthreads();

    __half* arow = g_attnh + (size_t)p * HID;
    for (int c = t; c < HID; c += 256) {
        int n = c / DH;
        int j = c - n * DH;
        float acc = 0.0f;
        #pragma unroll
        for (int m = 0; m < NHEADS; m++)
            acc += w[n * NHEADS + m] * vs[m * DH + j];
        arow[c] = __float2half_rn(acc);
    }
}

// ======================= residual + LayerNorm (single pass) ===============
__device__ __forceinline__ void block_sum2(float& a, float& b, float* red) {
    #pragma unroll
    for (int o = 16; o > 0; o >>= 1) {
        a += __shfl_xor_sync(0xFFFFFFFFu, a, o);
        b += __shfl_xor_sync(0xFFFFFFFFu, b, o);
    }
    int warp = threadIdx.x >> 5, lane = threadIdx.x & 31;
    if (lane == 0) { red[warp] = a; red[8 + warp] = b; }
    __syncthreads();
    if (warp == 0) {
        float x = (lane < 8) ? red[lane] : 0.0f;
        float y = (lane < 8) ? red[8 + lane] : 0.0f;
        #pragma unroll
        for (int o = 4; o > 0; o >>= 1) {
            x += __shfl_xor_sync(0xFFFFFFFFu, x, o);
            y += __shfl_xor_sync(0xFFFFFFFFu, y, o);
        }
        if (lane == 0) { red[0] = x; red[1] = y; }
    }
    __syncthreads();
    a = red[0];
    b = red[1];
    __syncthreads();
}

__global__ __launch_bounds__(256)
void ln_kernel(const float* __restrict__ x, const float* __restrict__ bo,
               const float* __restrict__ gamma, const float* __restrict__ beta,
               float* __restrict__ out) {
    __shared__ float ybuf[HID];
    __shared__ float red[16];

    int row = blockIdx.x;
    int t = threadIdx.x;
    const float* xr = x + (size_t)row * HID;
    const float* orow = g_o + (size_t)row * HID;

    float s = 0.0f, ss = 0.0f;
    for (int c = t; c < HID; c += 256) {
        float y = xr[c] + orow[c] + bo[c];
        ybuf[c] = y;
        s += y;
        ss += y * y;
    }
    block_sum2(s, ss, red);
    float mu = s * (1.0f / (float)HID);
    float var = ss * (1.0f / (float)HID) - mu * mu;
    float rstd = rsqrtf(var + 1e-5f);

    float* orow_out = out + (size_t)row * HID;
    for (int c = t; c < HID; c += 256) {
        orow_out[c] = (ybuf[c] - mu) * rstd * gamma[c] + beta[c];
    }
}

// ---------------------------------------------------------------------------
extern "C" void kernel_launch(void* const* d_in, const int* in_sizes, int n_in,
                              void* d_out, int out_size) {
    const float* x  = (const float*)d_in[0];
    const float* wq = (const float*)d_in[1];
    const float* bq = (const float*)d_in[2];
    const float* wk = (const float*)d_in[3];
    const float* bk = (const float*)d_in[4];
    const float* wv = (const float*)d_in[5];
    const float* bv = (const float*)d_in[6];
    const float* wo = (const float*)d_in[7];
    const float* bo = (const float*)d_in[8];
    const float* g  = (const float*)d_in[9];
    const float* bl = (const float*)d_in[10];
    float* out = (float*)d_out;

    int M = in_sizes[0] / HID;   // b*s = 8192

    float* o;
    __half *xh, *attnh, *wqkvh, *woh;
    cudaGetSymbolAddress((void**)&o,     g_o);
    cudaGetSymbolAddress((void**)&xh,    g_xh);
    cudaGetSymbolAddress((void**)&attnh, g_attnh);
    cudaGetSymbolAddress((void**)&wqkvh, g_wqkvh);
    cudaGetSymbolAddress((void**)&woh,   g_woh);

    static int smem_set = 0;
    if (!smem_set) {
        cudaFuncSetAttribute(gemm_qkv_kernel,
                             cudaFuncAttributeMaxDynamicSharedMemorySize, GEMM_SMEM_BYTES);
        cudaFuncSetAttribute(gemm_wo_kernel,
                             cudaFuncAttributeMaxDynamicSharedMemorySize, GEMM_SMEM_BYTES);
        smem_set = 1;
    }

    build_omega_kernel<<<(HALF_D + 255) / 256, 256>>>();
    build_rope_kernel<<<(SLEN * HALF_D + 255) / 256, 256>>>();

    {
        int nx4 = (M * HID) / 4;
        int nw4 = (HID * HID) / 4;
        int total = nx4 + 4 * nw4;
        convert_all_kernel<<<(total + 255) / 256, 256>>>(x, wq, wk, wv, wo,
                                                         xh, wqkvh, woh,
                                                         nx4, nw4);
    }

    dim3 qkvgrid(3 * HID / BN, M / BM);   // 54 x 64
    gemm_qkv_kernel<<<qkvgrid, 128, GEMM_SMEM_BYTES>>>(xh, wqkvh, bq, bk, bv, M, HID);

    attention_kernel<<<M, 256>>>(M);

    dim3 wogrid(HID / BN, M / BM);        // 18 x 64
    gemm_wo_kernel<<<wogrid, 128, GEMM_SMEM_BYTES>>>(attnh, woh, o, M, HID, HID);

    ln_kernel<<<M, 256>>>(x, bo, g, bl, out);

    (void)n_in; (void)out_size;
}

// round 15
// speedup vs baseline: 1.0518x; 1.0518x over previous
#include <cuda_runtime.h>
#include <cuda_fp16.h>
#include <math.h>
#include <cstdint>

#define HID    2304
#define HALF_D 1152
#define NHEADS 16
#define NH17   17
#define DH     144
#define SLEN   2048
#define MMAX   8192

// -------- scratch (static device globals; no runtime allocation) ----------
__device__ __half g_q16[(size_t)MMAX * HID];
__device__ __half g_k16[(size_t)MMAX * HID];
__device__ __half g_v16[(size_t)MMAX * HID];
__device__ float  g_o[(size_t)MMAX * HID];
__device__ __half g_xh[(size_t)MMAX * HID];
__device__ __half g_attnh[(size_t)MMAX * HID];
__device__ __half g_wqkvh[(size_t)3 * HID * HID];   // packed [3*HID, HID]
__device__ __half g_woh[(size_t)HID * HID];
__device__ float  g_cos[SLEN * HALF_D];
__device__ float  g_sin[SLEN * HALF_D];
__device__ double g_omega[HALF_D];

// ---------------------------------------------------------------------------
// RoPE tables.
// ---------------------------------------------------------------------------
__global__ void build_omega_kernel() {
    int i = blockIdx.x * blockDim.x + threadIdx.x;
    if (i < HALF_D) {
        double scale = (2.0 * (double)i) / (double)HID;
        g_omega[i] = exp(-scale * log(10000.0));
    }
}

__global__ void build_rope_kernel() {
    int idx = blockIdx.x * blockDim.x + threadIdx.x;
    if (idx >= SLEN * HALF_D) return;
    int pos = idx / HALF_D;
    int i   = idx - pos * HALF_D;
    double ang = (double)pos * g_omega[i];
    double n = floor(ang * 0.15915494309189535);
    double r = ang - n * 6.283185307179586476925286766559;
    float s, c;
    sincosf((float)r, &s, &c);
    g_cos[idx] = c;
    g_sin[idx] = s;
}

// ---------------------------------------------------------------------------
// One-shot conversion, direct-indexed (one float4 per thread, one branch).
// ---------------------------------------------------------------------------
__global__ void convert_all_kernel(const float* __restrict__ x,
                                   const float* __restrict__ wq,
                                   const float* __restrict__ wk,
                                   const float* __restrict__ wv,
                                   const float* __restrict__ wo,
                                   __half* __restrict__ xh,
                                   __half* __restrict__ wqkvh,
                                   __half* __restrict__ woh,
                                   int nx4, int nw4) {
    int i = blockIdx.x * blockDim.x + threadIdx.x;
    int total = nx4 + 4 * nw4;
    if (i >= total) return;
    const float* src;
    __half* dst;
    int idx;
    if (i < nx4) {
        src = x; dst = xh; idx = i;
    } else {
        int j = i - nx4;
        int w = j / nw4;       // 0..3
        idx = j - w * nw4;
        src = (w == 0) ? wq : (w == 1) ? wk : (w == 2) ? wv : wo;
        dst = (w == 0) ? wqkvh
            : (w == 1) ? wqkvh + (size_t)HID * HID
            : (w == 2) ? wqkvh + (size_t)2 * HID * HID
            : woh;
    }
    float4 v = ((const float4*)src)[idx];
    ((__half2*)dst)[2 * idx]     = __floats2half2_rn(v.x, v.y);
    ((__half2*)dst)[2 * idx + 1] = __floats2half2_rn(v.z, v.w);
}

// ---------------------------------------------------------------------------
// PTX helpers
// ---------------------------------------------------------------------------
__device__ __forceinline__ void cp_async16(uint32_t dst, const void* src) {
    asm volatile("cp.async.cg.shared.global [%0], [%1], 16;\n" :: "r"(dst), "l"(src));
}
__device__ __forceinline__ void cp_commit() {
    asm volatile("cp.async.commit_group;\n");
}
__device__ __forceinline__ void cp_wait1() {
    asm volatile("cp.async.wait_group 1;\n");
}

#define LDSM4(r0, r1, r2, r3, addr) \
    asm volatile("ldmatrix.sync.aligned.m8n8.x4.shared.b16 {%0,%1,%2,%3}, [%4];" \
                 : "=r"(r0), "=r"(r1), "=r"(r2), "=r"(r3) : "r"(addr))

#define MMA_F16(d, a0, a1, a2, a3, b0, b1) \
    asm volatile("mma.sync.aligned.m16n8k16.row.col.f32.f16.f16.f32 " \
                 "{%0,%1,%2,%3}, {%4,%5,%6,%7}, {%8,%9}, {%0,%1,%2,%3};" \
                 : "+f"((d)[0]), "+f"((d)[1]), "+f"((d)[2]), "+f"((d)[3]) \
                 : "r"(a0), "r"(a1), "r"(a2), "r"(a3), "r"(b0), "r"(b1))

// ---------------------------------------------------------------------------
// GEMM core: CTA tile 128x128, 128 threads (4 warps, 64x64), 2 CTAs/SM,
// 3-stage cp.async pipeline + LDSM double-buffering (R13 schedule).
// ---------------------------------------------------------------------------
#define BM 128
#define BN 128
#define BKH 64                              // K halfs per stage (128 bytes)
#define A_BYTES (BM * 128)
#define B_BYTES (BN * 128)
#define STAGE_BYTES (A_BYTES + B_BYTES)     // 32768
#define GEMM_SMEM_BYTES (3 * STAGE_BYTES)   // 98304 per CTA

__device__ __forceinline__ void load_stage(const __half* __restrict__ A,
                                           const __half* __restrict__ B,
                                           int K, int bm, int bn, int k0,
                                           uint32_t stg, int tid) {
    #pragma unroll
    for (int i = 0; i < 8; i++) {
        int e = i * 128 + tid;
        int r = e >> 3;
        int cb = (e & 7) * 16;
        cp_async16(stg + r * 128 + (cb ^ ((r & 7) << 4)),
                   A + (size_t)(bm + r) * K + k0 + (e & 7) * 8);
    }
    #pragma unroll
    for (int i = 0; i < 8; i++) {
        int e = i * 128 + tid;
        int r = e >> 3;
        int cb = (e & 7) * 16;
        cp_async16(stg + A_BYTES + r * 128 + (cb ^ ((r & 7) << 4)),
                   B + (size_t)(bn + r) * K + k0 + (e & 7) * 8);
    }
}

struct Frag { uint32_t a[4][4]; uint32_t b[4][4]; };

__device__ __forceinline__ void ldsm_all(Frag& f, uint32_t stg, int kk,
                                         const int* rowA, const int* rowB,
                                         int lh, int lc) {
    const int kbL = kk * 32;
    #pragma unroll
    for (int mb = 0; mb < 4; mb++) {
        uint32_t ad = stg + rowA[mb] * 128 +
                      ((kbL + lc * 16) ^ ((rowA[mb] & 7) << 4));
        LDSM4(f.a[mb][0], f.a[mb][1], f.a[mb][2], f.a[mb][3], ad);
    }
    #pragma unroll
    for (int j = 0; j < 4; j++) {
        uint32_t bd = stg + A_BYTES + rowB[j] * 128 +
                      ((kbL + lh * 16) ^ ((rowB[j] & 7) << 4));
        LDSM4(f.b[j][0], f.b[j][1], f.b[j][2], f.b[j][3], bd);
    }
}

__device__ __forceinline__ void mma_all(float acc[4][8][4], const Frag& f) {
    #pragma unroll
    for (int mb = 0; mb < 4; mb++)
        #pragma unroll
        for (int j = 0; j < 4; j++) {
            MMA_F16(acc[mb][2 * j],     f.a[mb][0], f.a[mb][1], f.a[mb][2], f.a[mb][3],
                    f.b[j][0], f.b[j][1]);
            MMA_F16(acc[mb][2 * j + 1], f.a[mb][0], f.a[mb][1], f.a[mb][2], f.a[mb][3],
                    f.b[j][2], f.b[j][3]);
        }
}

__device__ __forceinline__ void gemm_mainloop(const __half* A, const __half* B,
                                              int K, int bm, int bn,
                                              uint32_t sbase, int tid,
                                              const int* rowA, const int* rowB,
                                              int lh, int lc,
                                              float acc[4][8][4]) {
    const int kIters = K / BKH;   // 36

    load_stage(A, B, K, bm, bn, 0, sbase, tid);
    cp_commit();
    load_stage(A, B, K, bm, bn, BKH, sbase + STAGE_BYTES, tid);
    cp_commit();

    int stage = 0;
    for (int kt = 0; kt < kIters; kt++) {
        cp_wait1();
        __syncthreads();

        int nk = kt + 2;
        if (nk < kIters)
            load_stage(A, B, K, bm, bn, nk * BKH,
                       sbase + (nk % 3) * STAGE_BYTES, tid);
        cp_commit();

        const uint32_t stg = sbase + stage * STAGE_BYTES;

        Frag f[2];
        ldsm_all(f[0], stg, 0, rowA, rowB, lh, lc);
        #pragma unroll
        for (int kk = 0; kk < 4; kk++) {
            int cur = kk & 1;
            if (kk < 3) ldsm_all(f[cur ^ 1], stg, kk + 1, rowA, rowB, lh, lc);
            mma_all(acc, f[cur]);
        }

        stage = (stage + 1 == 3) ? 0 : stage + 1;
    }
}

// ---------------------------------------------------------------------------
// Fused q/k/v projection: B packed [3*HID, HID]; per-CTA sel picks output.
// ---------------------------------------------------------------------------
__global__ __launch_bounds__(128, 2)
void gemm_qkv_kernel(const __half* __restrict__ A, const __half* __restrict__ B,
                     const float* __restrict__ bq, const float* __restrict__ bk,
                     const float* __restrict__ bv, int M, int K) {
    extern __shared__ char smem[];
    uint32_t sbase;
    asm("{ .reg .u64 t; cvta.to.shared.u64 t, %1; cvt.u32.u64 %0, t; }"
        : "=r"(sbase) : "l"(smem));

    const int tid  = threadIdx.x;
    const int warp = tid >> 5;
    const int lane = tid & 31;
    const int bm = blockIdx.y * BM;
    const int bn = blockIdx.x * BN;
    const int wm = (warp >> 1) * 64;
    const int wn = (warp & 1) * 64;

    const int lr = lane & 7;
    const int lh = (lane >> 3) & 1;
    const int lc = lane >> 4;

    int rowA[4], rowB[4];
    #pragma unroll
    for (int mb = 0; mb < 4; mb++) rowA[mb] = wm + mb * 16 + lr + lh * 8;
    #pragma unroll
    for (int j = 0; j < 4; j++)    rowB[j] = wn + j * 16 + lr + lc * 8;

    float acc[4][8][4];
    #pragma unroll
    for (int mb = 0; mb < 4; mb++)
        #pragma unroll
        for (int nb = 0; nb < 8; nb++)
            #pragma unroll
            for (int e = 0; e < 4; e++) acc[mb][nb][e] = 0.0f;

    gemm_mainloop(A, B, K, bm, bn, sbase, tid, rowA, rowB, lh, lc, acc);

    // ---- epilogue: per-CTA uniform output selection ----
    const int sel   = bn / HID;              // 0=q, 1=k, 2=v
    const int cbase = bn - sel * HID;
    const float* bias = (sel == 0) ? bq : (sel == 1) ? bk : bv;
    __half* Ch = (sel == 0) ? g_q16 : (sel == 1) ? g_k16 : g_v16;

    #pragma unroll
    for (int mb = 0; mb < 4; mb++) {
        const int r0 = bm + wm + mb * 16 + (lane >> 2);
        #pragma unroll
        for (int nb = 0; nb < 8; nb++) {
            const int lcol = cbase + wn + nb * 8 + (lane & 3) * 2;
            float x0 = acc[mb][nb][0], x1 = acc[mb][nb][1];
            float y0 = acc[mb][nb][2], y1 = acc[mb][nb][3];
            float2 bb = *(const float2*)(bias + lcol);
            x0 += bb.x; x1 += bb.y;
            y0 += bb.x; y1 += bb.y;
            if (sel < 2) {   // RoPE for q, k
                const int i = lcol >> 1;
                const int p0 = r0 & (SLEN - 1);
                const int p1 = (r0 + 8) & (SLEN - 1);
                float c0 = g_cos[p0 * HALF_D + i], s0 = g_sin[p0 * HALF_D + i];
                float c1 = g_cos[p1 * HALF_D + i], s1 = g_sin[p1 * HALF_D + i];
                float t0 = c0 * x0 - s0 * x1;
                float t1 = s0 * x0 + c0 * x1;
                x0 = t0; x1 = t1;
                t0 = c1 * y0 - s1 * y1;
                t1 = s1 * y0 + c1 * y1;
                y0 = t0; y1 = t1;
            }
            *(__half2*)(Ch + (size_t)r0 * HID + lcol)       = __floats2half2_rn(x0, x1);
            *(__half2*)(Ch + (size_t)(r0 + 8) * HID + lcol) = __floats2half2_rn(y0, y1);
        }
    }
}

// ---------------------------------------------------------------------------
// Output projection GEMM: plain f32 store.
// ---------------------------------------------------------------------------
__global__ __launch_bounds__(128, 2)
void gemm_wo_kernel(const __half* __restrict__ A, const __half* __restrict__ B,
                    float* __restrict__ C, int M, int N, int K) {
    extern __shared__ char smem[];
    uint32_t sbase;
    asm("{ .reg .u64 t; cvta.to.shared.u64 t, %1; cvt.u32.u64 %0, t; }"
        : "=r"(sbase) : "l"(smem));

    const int tid  = threadIdx.x;
    const int warp = tid >> 5;
    const int lane = tid & 31;
    const int bm = blockIdx.y * BM;
    const int bn = blockIdx.x * BN;
    const int wm = (warp >> 1) * 64;
    const int wn = (warp & 1) * 64;

    const int lr = lane & 7;
    const int lh = (lane >> 3) & 1;
    const int lc = lane >> 4;

    int rowA[4], rowB[4];
    #pragma unroll
    for (int mb = 0; mb < 4; mb++) rowA[mb] = wm + mb * 16 + lr + lh * 8;
    #pragma unroll
    for (int j = 0; j < 4; j++)    rowB[j] = wn + j * 16 + lr + lc * 8;

    float acc[4][8][4];
    #pragma unroll
    for (int mb = 0; mb < 4; mb++)
        #pragma unroll
        for (int nb = 0; nb < 8; nb++)
            #pragma unroll
            for (int e = 0; e < 4; e++) acc[mb][nb][e] = 0.0f;

    gemm_mainloop(A, B, K, bm, bn, sbase, tid, rowA, rowB, lh, lc, acc);

    #pragma unroll
    for (int mb = 0; mb < 4; mb++) {
        const int r0 = bm + wm + mb * 16 + (lane >> 2);
        #pragma unroll
        for (int nb = 0; nb < 8; nb++) {
            const int gc = bn + wn + nb * 8 + (lane & 3) * 2;
            *(float2*)(C + (size_t)r0 * N + gc) =
                make_float2(acc[mb][nb][0], acc[mb][nb][1]);
            *(float2*)(C + (size_t)(r0 + 8) * N + gc) =
                make_float2(acc[mb][nb][2], acc[mb][nb][3]);
        }
    }
}

// ======================= head-mixing attention =============================
__global__ __launch_bounds__(256)
void attention_kernel(int M) {
    __shared__ float qt[DH * NH17];
    __shared__ float kt[DH * NH17];
    __shared__ float vs[HID];
    __shared__ float w[NHEADS * NHEADS];

    int p = blockIdx.x;
    int t = threadIdx.x;
    const __half2* qrow = (const __half2*)(g_q16 + (size_t)p * HID);
    const __half2* krow = (const __half2*)(g_k16 + (size_t)p * HID);
    const __half2* vrow = (const __half2*)(g_v16 + (size_t)p * HID);

    for (int c2 = t; c2 < HID / 2; c2 += 256) {
        int c = 2 * c2;
        int n = c / DH;
        int j = c - n * DH;
        float2 qf = __half22float2(qrow[c2]);
        float2 kf = __half22float2(krow[c2]);
        float2 vf = __half22float2(vrow[c2]);
        qt[j * NH17 + n] = qf.x;
        qt[(j + 1) * NH17 + n] = qf.y;
        kt[j * NH17 + n] = kf.x;
        kt[(j + 1) * NH17 + n] = kf.y;
        vs[c] = vf.x;
        vs[c + 1] = vf.y;
    }
    __syncthreads();

    {
        int m = t >> 4;
        int n = t & 15;
        float acc = 0.0f;
        #pragma unroll 8
        for (int j = 0; j < DH; j++)
            acc += qt[j * NH17 + n] * kt[j * NH17 + m];
        w[n * NHEADS + m] = acc * (1.0f / 12.0f);
    }
    __syncthreads();

    if (t < NHEADS) {
        float mx = -1e30f;
        #pragma unroll
        for (int m = 0; m < NHEADS; m++) mx = fmaxf(mx, w[t * NHEADS + m]);
        float sum = 0.0f;
        #pragma unroll
        for (int m = 0; m < NHEADS; m++) {
            float e = expf(w[t * NHEADS + m] - mx);
            w[t * NHEADS + m] = e;
            sum += e;
        }
        float inv = 1.0f / sum;
        #pragma unroll
        for (int m = 0; m < NHEADS; m++) w[t * NHEADS + m] *= inv;
    }
    __syncthreads();

    __half* arow = g_attnh + (size_t)p * HID;
    for (int c = t; c < HID; c += 256) {
        int n = c / DH;
        int j = c - n * DH;
        float acc = 0.0f;
        #pragma unroll
        for (int m = 0; m < NHEADS; m++)
            acc += w[n * NHEADS + m] * vs[m * DH + j];
        arow[c] = __float2half_rn(acc);
    }
}

// ======================= residual + LayerNorm (single pass) ===============
__device__ __forceinline__ void block_sum2(float& a, float& b, float* red) {
    #pragma unroll
    for (int o = 16; o > 0; o >>= 1) {
        a += __shfl_xor_sync(0xFFFFFFFFu, a, o);
        b += __shfl_xor_sync(0xFFFFFFFFu, b, o);
    }
    int warp = threadIdx.x >> 5, lane = threadIdx.x & 31;
    if (lane == 0) { red[warp] = a; red[8 + warp] = b; }
    __syncthreads();
    if (warp == 0) {
        float x = (lane < 8) ? red[lane] : 0.0f;
        float y = (lane < 8) ? red[8 + lane] : 0.0f;
        #pragma unroll
        for (int o = 4; o > 0; o >>= 1) {
            x += __shfl_xor_sync(0xFFFFFFFFu, x, o);
            y += __shfl_xor_sync(0xFFFFFFFFu, y, o);
        }
        if (lane == 0) { red[0] = x; red[1] = y; }
    }
    __syncthreads();
    a = red[0];
    b = red[1];
    __syncthreads();
}

__global__ __launch_bounds__(256)
void ln_kernel(const float* __restrict__ x, const float* __restrict__ bo,
               const float* __restrict__ gamma, const float* __restrict__ beta,
               float* __restrict__ out) {
    __shared__ float ybuf[HID];
    __shared__ float red[16];

    int row = blockIdx.x;
    int t = threadIdx.x;
    const float* xr = x + (size_t)row * HID;
    const float* orow = g_o + (size_t)row * HID;

    float s = 0.0f, ss = 0.0f;
    for (int c = t; c < HID; c += 256) {
        float y = xr[c] + orow[c] + bo[c];
        ybuf[c] = y;
        s += y;
        ss += y * y;
    }
    block_sum2(s, ss, red);
    float mu = s * (1.0f / (float)HID);
    float var = ss * (1.0f / (float)HID) - mu * mu;
    float rstd = rsqrtf(var + 1e-5f);

    float* orow_out = out + (size_t)row * HID;
    for (int c = t; c < HID; c += 256) {
        orow_out[c] = (ybuf[c] - mu) * rstd * gamma[c] + beta[c];
    }
}

// ---------------------------------------------------------------------------
extern "C" void kernel_launch(void* const* d_in, const int* in_sizes, int n_in,
                              void* d_out, int out_size) {
    const float* x  = (const float*)d_in[0];
    const float* wq = (const float*)d_in[1];
    const float* bq = (const float*)d_in[2];
    const float* wk = (const float*)d_in[3];
    const float* bk = (const float*)d_in[4];
    const float* wv = (const float*)d_in[5];
    const float* bv = (const float*)d_in[6];
    const float* wo = (const float*)d_in[7];
    const float* bo = (const float*)d_in[8];
    const float* g  = (const float*)d_in[9];
    const float* bl = (const float*)d_in[10];
    float* out = (float*)d_out;

    int M = in_sizes[0] / HID;   // b*s = 8192

    float* o;
    __half *xh, *attnh, *wqkvh, *woh;
    cudaGetSymbolAddress((void**)&o,     g_o);
    cudaGetSymbolAddress((void**)&xh,    g_xh);
    cudaGetSymbolAddress((void**)&attnh, g_attnh);
    cudaGetSymbolAddress((void**)&wqkvh, g_wqkvh);
    cudaGetSymbolAddress((void**)&woh,   g_woh);

    static int smem_set = 0;
    if (!smem_set) {
        cudaFuncSetAttribute(gemm_qkv_kernel,
                             cudaFuncAttributeMaxDynamicSharedMemorySize, GEMM_SMEM_BYTES);
        cudaFuncSetAttribute(gemm_wo_kernel,
                             cudaFuncAttributeMaxDynamicSharedMemorySize, GEMM_SMEM_BYTES);
        smem_set = 1;
    }

    build_omega_kernel<<<(HALF_D + 255) / 256, 256>>>();
    build_rope_kernel<<<(SLEN * HALF_D + 255) / 256, 256>>>();

    {
        int nx4 = (M * HID) / 4;
        int nw4 = (HID * HID) / 4;
        int total = nx4 + 4 * nw4;
        convert_all_kernel<<<(total + 255) / 256, 256>>>(x, wq, wk, wv, wo,
                                                         xh, wqkvh, woh,
                                                         nx4, nw4);
    }

    dim3 qkvgrid(3 * HID / BN, M / BM);   // 54 x 64
    gemm_qkv_kernel<<<qkvgrid, 128, GEMM_SMEM_BYTES>>>(xh, wqkvh, bq, bk, bv, M, HID);

    attention_kernel<<<M, 256>>>(M);

    dim3 wogrid(HID / BN, M / BM);        // 18 x 64
    gemm_wo_kernel<<<wogrid, 128, GEMM_SMEM_BYTES>>>(attnh, woh, o, M, HID, HID);

    ln_kernel<<<M, 256>>>(x, bo, g, bl, out);

    (void)n_in; (void)out_size;
}

// round 16
// speedup vs baseline: 1.0697x; 1.0171x over previous
#include <cuda_runtime.h>
#include <cuda_fp16.h>
#include <math.h>
#include <cstdint>

#define HID    2304
#define HALF_D 1152
#define NHEADS 16
#define NH17   17
#define DH     144
#define SLEN   2048
#define MMAX   8192

// -------- scratch (static device globals; no runtime allocation) ----------
__device__ __half g_q16[(size_t)MMAX * HID];
__device__ __half g_k16[(size_t)MMAX * HID];
__device__ __half g_v16[(size_t)MMAX * HID];
__device__ __half g_o16[(size_t)MMAX * HID];     // fp16 wo-GEMM output
__device__ __half g_xh[(size_t)MMAX * HID];
__device__ __half g_attnh[(size_t)MMAX * HID];
__device__ __half g_wqkvh[(size_t)3 * HID * HID];   // packed [3*HID, HID]
__device__ __half g_woh[(size_t)HID * HID];
__device__ float  g_cos[SLEN * HALF_D];
__device__ float  g_sin[SLEN * HALF_D];
__device__ double g_omega[HALF_D];

// ---------------------------------------------------------------------------
// RoPE tables.
// ---------------------------------------------------------------------------
__global__ void build_omega_kernel() {
    int i = blockIdx.x * blockDim.x + threadIdx.x;
    if (i < HALF_D) {
        double scale = (2.0 * (double)i) / (double)HID;
        g_omega[i] = exp(-scale * log(10000.0));
    }
}

__global__ void build_rope_kernel() {
    int idx = blockIdx.x * blockDim.x + threadIdx.x;
    if (idx >= SLEN * HALF_D) return;
    int pos = idx / HALF_D;
    int i   = idx - pos * HALF_D;
    double ang = (double)pos * g_omega[i];
    double n = floor(ang * 0.15915494309189535);
    double r = ang - n * 6.283185307179586476925286766559;
    float s, c;
    sincosf((float)r, &s, &c);
    g_cos[idx] = c;
    g_sin[idx] = s;
}

// ---------------------------------------------------------------------------
// One-shot conversion, direct-indexed (one float4 per thread, one branch).
// ---------------------------------------------------------------------------
__global__ void convert_all_kernel(const float* __restrict__ x,
                                   const float* __restrict__ wq,
                                   const float* __restrict__ wk,
                                   const float* __restrict__ wv,
                                   const float* __restrict__ wo,
                                   __half* __restrict__ xh,
                                   __half* __restrict__ wqkvh,
                                   __half* __restrict__ woh,
                                   int nx4, int nw4) {
    int i = blockIdx.x * blockDim.x + threadIdx.x;
    int total = nx4 + 4 * nw4;
    if (i >= total) return;
    const float* src;
    __half* dst;
    int idx;
    if (i < nx4) {
        src = x; dst = xh; idx = i;
    } else {
        int j = i - nx4;
        int w = j / nw4;       // 0..3
        idx = j - w * nw4;
        src = (w == 0) ? wq : (w == 1) ? wk : (w == 2) ? wv : wo;
        dst = (w == 0) ? wqkvh
            : (w == 1) ? wqkvh + (size_t)HID * HID
            : (w == 2) ? wqkvh + (size_t)2 * HID * HID
            : woh;
    }
    float4 v = ((const float4*)src)[idx];
    ((__half2*)dst)[2 * idx]     = __floats2half2_rn(v.x, v.y);
    ((__half2*)dst)[2 * idx + 1] = __floats2half2_rn(v.z, v.w);
}

// ---------------------------------------------------------------------------
// PTX helpers
// ---------------------------------------------------------------------------
__device__ __forceinline__ void cp_async16(uint32_t dst, const void* src) {
    asm volatile("cp.async.cg.shared.global [%0], [%1], 16;\n" :: "r"(dst), "l"(src));
}
__device__ __forceinline__ void cp_commit() {
    asm volatile("cp.async.commit_group;\n");
}
__device__ __forceinline__ void cp_wait1() {
    asm volatile("cp.async.wait_group 1;\n");
}

#define LDSM4(r0, r1, r2, r3, addr) \
    asm volatile("ldmatrix.sync.aligned.m8n8.x4.shared.b16 {%0,%1,%2,%3}, [%4];" \
                 : "=r"(r0), "=r"(r1), "=r"(r2), "=r"(r3) : "r"(addr))

#define MMA_F16(d, a0, a1, a2, a3, b0, b1) \
    asm volatile("mma.sync.aligned.m16n8k16.row.col.f32.f16.f16.f32 " \
                 "{%0,%1,%2,%3}, {%4,%5,%6,%7}, {%8,%9}, {%0,%1,%2,%3};" \
                 : "+f"((d)[0]), "+f"((d)[1]), "+f"((d)[2]), "+f"((d)[3]) \
                 : "r"(a0), "r"(a1), "r"(a2), "r"(a3), "r"(b0), "r"(b1))

// ---------------------------------------------------------------------------
// GEMM core: CTA tile 128x128, 128 threads (4 warps, 64x64), 2 CTAs/SM,
// 3-stage cp.async pipeline + LDSM double-buffering (R13 schedule).
// ---------------------------------------------------------------------------
#define BM 128
#define BN 128
#define BKH 64                              // K halfs per stage (128 bytes)
#define A_BYTES (BM * 128)
#define B_BYTES (BN * 128)
#define STAGE_BYTES (A_BYTES + B_BYTES)     // 32768
#define GEMM_SMEM_BYTES (3 * STAGE_BYTES)   // 98304 per CTA

__device__ __forceinline__ void load_stage(const __half* __restrict__ A,
                                           const __half* __restrict__ B,
                                           int K, int bm, int bn, int k0,
                                           uint32_t stg, int tid) {
    #pragma unroll
    for (int i = 0; i < 8; i++) {
        int e = i * 128 + tid;
        int r = e >> 3;
        int cb = (e & 7) * 16;
        cp_async16(stg + r * 128 + (cb ^ ((r & 7) << 4)),
                   A + (size_t)(bm + r) * K + k0 + (e & 7) * 8);
    }
    #pragma unroll
    for (int i = 0; i < 8; i++) {
        int e = i * 128 + tid;
        int r = e >> 3;
        int cb = (e & 7) * 16;
        cp_async16(stg + A_BYTES + r * 128 + (cb ^ ((r & 7) << 4)),
                   B + (size_t)(bn + r) * K + k0 + (e & 7) * 8);
    }
}

struct Frag { uint32_t a[4][4]; uint32_t b[4][4]; };

__device__ __forceinline__ void ldsm_all(Frag& f, uint32_t stg, int kk,
                                         const int* rowA, const int* rowB,
                                         int lh, int lc) {
    const int kbL = kk * 32;
    #pragma unroll
    for (int mb = 0; mb < 4; mb++) {
        uint32_t ad = stg + rowA[mb] * 128 +
                      ((kbL + lc * 16) ^ ((rowA[mb] & 7) << 4));
        LDSM4(f.a[mb][0], f.a[mb][1], f.a[mb][2], f.a[mb][3], ad);
    }
    #pragma unroll
    for (int j = 0; j < 4; j++) {
        uint32_t bd = stg + A_BYTES + rowB[j] * 128 +
                      ((kbL + lh * 16) ^ ((rowB[j] & 7) << 4));
        LDSM4(f.b[j][0], f.b[j][1], f.b[j][2], f.b[j][3], bd);
    }
}

__device__ __forceinline__ void mma_all(float acc[4][8][4], const Frag& f) {
    #pragma unroll
    for (int mb = 0; mb < 4; mb++)
        #pragma unroll
        for (int j = 0; j < 4; j++) {
            MMA_F16(acc[mb][2 * j],     f.a[mb][0], f.a[mb][1], f.a[mb][2], f.a[mb][3],
                    f.b[j][0], f.b[j][1]);
            MMA_F16(acc[mb][2 * j + 1], f.a[mb][0], f.a[mb][1], f.a[mb][2], f.a[mb][3],
                    f.b[j][2], f.b[j][3]);
        }
}

__device__ __forceinline__ void gemm_mainloop(const __half* A, const __half* B,
                                              int K, int bm, int bn,
                                              uint32_t sbase, int tid,
                                              const int* rowA, const int* rowB,
                                              int lh, int lc,
                                              float acc[4][8][4]) {
    const int kIters = K / BKH;   // 36

    load_stage(A, B, K, bm, bn, 0, sbase, tid);
    cp_commit();
    load_stage(A, B, K, bm, bn, BKH, sbase + STAGE_BYTES, tid);
    cp_commit();

    int stage = 0;
    for (int kt = 0; kt < kIters; kt++) {
        cp_wait1();
        __syncthreads();

        int nk = kt + 2;
        if (nk < kIters)
            load_stage(A, B, K, bm, bn, nk * BKH,
                       sbase + (nk % 3) * STAGE_BYTES, tid);
        cp_commit();

        const uint32_t stg = sbase + stage * STAGE_BYTES;

        Frag f[2];
        ldsm_all(f[0], stg, 0, rowA, rowB, lh, lc);
        #pragma unroll
        for (int kk = 0; kk < 4; kk++) {
            int cur = kk & 1;
            if (kk < 3) ldsm_all(f[cur ^ 1], stg, kk + 1, rowA, rowB, lh, lc);
            mma_all(acc, f[cur]);
        }

        stage = (stage + 1 == 3) ? 0 : stage + 1;
    }
}

// ---------------------------------------------------------------------------
// Fused q/k/v projection: B packed [3*HID, HID]; per-CTA sel picks output.
// ---------------------------------------------------------------------------
__global__ __launch_bounds__(128, 2)
void gemm_qkv_kernel(const __half* __restrict__ A, const __half* __restrict__ B,
                     const float* __restrict__ bq, const float* __restrict__ bk,
                     const float* __restrict__ bv, int M, int K) {
    extern __shared__ char smem[];
    uint32_t sbase;
    asm("{ .reg .u64 t; cvta.to.shared.u64 t, %1; cvt.u32.u64 %0, t; }"
        : "=r"(sbase) : "l"(smem));

    const int tid  = threadIdx.x;
    const int warp = tid >> 5;
    const int lane = tid & 31;
    const int bm = blockIdx.y * BM;
    const int bn = blockIdx.x * BN;
    const int wm = (warp >> 1) * 64;
    const int wn = (warp & 1) * 64;

    const int lr = lane & 7;
    const int lh = (lane >> 3) & 1;
    const int lc = lane >> 4;

    int rowA[4], rowB[4];
    #pragma unroll
    for (int mb = 0; mb < 4; mb++) rowA[mb] = wm + mb * 16 + lr + lh * 8;
    #pragma unroll
    for (int j = 0; j < 4; j++)    rowB[j] = wn + j * 16 + lr + lc * 8;

    float acc[4][8][4];
    #pragma unroll
    for (int mb = 0; mb < 4; mb++)
        #pragma unroll
        for (int nb = 0; nb < 8; nb++)
            #pragma unroll
            for (int e = 0; e < 4; e++) acc[mb][nb][e] = 0.0f;

    gemm_mainloop(A, B, K, bm, bn, sbase, tid, rowA, rowB, lh, lc, acc);

    // ---- epilogue: per-CTA uniform output selection ----
    const int sel   = bn / HID;              // 0=q, 1=k, 2=v
    const int cbase = bn - sel * HID;
    const float* bias = (sel == 0) ? bq : (sel == 1) ? bk : bv;
    __half* Ch = (sel == 0) ? g_q16 : (sel == 1) ? g_k16 : g_v16;

    #pragma unroll
    for (int mb = 0; mb < 4; mb++) {
        const int r0 = bm + wm + mb * 16 + (lane >> 2);
        #pragma unroll
        for (int nb = 0; nb < 8; nb++) {
            const int lcol = cbase + wn + nb * 8 + (lane & 3) * 2;
            float x0 = acc[mb][nb][0], x1 = acc[mb][nb][1];
            float y0 = acc[mb][nb][2], y1 = acc[mb][nb][3];
            float2 bb = *(const float2*)(bias + lcol);
            x0 += bb.x; x1 += bb.y;
            y0 += bb.x; y1 += bb.y;
            if (sel < 2) {   // RoPE for q, k
                const int i = lcol >> 1;
                const int p0 = r0 & (SLEN - 1);
                const int p1 = (r0 + 8) & (SLEN - 1);
                float c0 = g_cos[p0 * HALF_D + i], s0 = g_sin[p0 * HALF_D + i];
                float c1 = g_cos[p1 * HALF_D + i], s1 = g_sin[p1 * HALF_D + i];
                float t0 = c0 * x0 - s0 * x1;
                float t1 = s0 * x0 + c0 * x1;
                x0 = t0; x1 = t1;
                t0 = c1 * y0 - s1 * y1;
                t1 = s1 * y0 + c1 * y1;
                y0 = t0; y1 = t1;
            }
            *(__half2*)(Ch + (size_t)r0 * HID + lcol)       = __floats2half2_rn(x0, x1);
            *(__half2*)(Ch + (size_t)(r0 + 8) * HID + lcol) = __floats2half2_rn(y0, y1);
        }
    }
}

// ---------------------------------------------------------------------------
// Output projection GEMM: fp16 store (feeds LN).
// ---------------------------------------------------------------------------
__global__ __launch_bounds__(128, 2)
void gemm_wo_kernel(const __half* __restrict__ A, const __half* __restrict__ B,
                    __half* __restrict__ C, int M, int N, int K) {
    extern __shared__ char smem[];
    uint32_t sbase;
    asm("{ .reg .u64 t; cvta.to.shared.u64 t, %1; cvt.u32.u64 %0, t; }"
        : "=r"(sbase) : "l"(smem));

    const int tid  = threadIdx.x;
    const int warp = tid >> 5;
    const int lane = tid & 31;
    const int bm = blockIdx.y * BM;
    const int bn = blockIdx.x * BN;
    const int wm = (warp >> 1) * 64;
    const int wn = (warp & 1) * 64;

    const int lr = lane & 7;
    const int lh = (lane >> 3) & 1;
    const int lc = lane >> 4;

    int rowA[4], rowB[4];
    #pragma unroll
    for (int mb = 0; mb < 4; mb++) rowA[mb] = wm + mb * 16 + lr + lh * 8;
    #pragma unroll
    for (int j = 0; j < 4; j++)    rowB[j] = wn + j * 16 + lr + lc * 8;

    float acc[4][8][4];
    #pragma unroll
    for (int mb = 0; mb < 4; mb++)
        #pragma unroll
        for (int nb = 0; nb < 8; nb++)
            #pragma unroll
            for (int e = 0; e < 4; e++) acc[mb][nb][e] = 0.0f;

    gemm_mainloop(A, B, K, bm, bn, sbase, tid, rowA, rowB, lh, lc, acc);

    #pragma unroll
    for (int mb = 0; mb < 4; mb++) {
        const int r0 = bm + wm + mb * 16 + (lane >> 2);
        #pragma unroll
        for (int nb = 0; nb < 8; nb++) {
            const int gc = bn + wn + nb * 8 + (lane & 3) * 2;
            *(__half2*)(C + (size_t)r0 * N + gc) =
                __floats2half2_rn(acc[mb][nb][0], acc[mb][nb][1]);
            *(__half2*)(C + (size_t)(r0 + 8) * N + gc) =
                __floats2half2_rn(acc[mb][nb][2], acc[mb][nb][3]);
        }
    }
}

// ======================= head-mixing attention =============================
__global__ __launch_bounds__(256)
void attention_kernel(int M) {
    __shared__ float qt[DH * NH17];
    __shared__ float kt[DH * NH17];
    __shared__ float vs[HID];
    __shared__ float w[NHEADS * NHEADS];

    int p = blockIdx.x;
    int t = threadIdx.x;
    const __half2* qrow = (const __half2*)(g_q16 + (size_t)p * HID);
    const __half2* krow = (const __half2*)(g_k16 + (size_t)p * HID);
    const __half2* vrow = (const __half2*)(g_v16 + (size_t)p * HID);

    for (int c2 = t; c2 < HID / 2; c2 += 256) {
        int c = 2 * c2;
        int n = c / DH;
        int j = c - n * DH;
        float2 qf = __half22float2(qrow[c2]);
        float2 kf = __half22float2(krow[c2]);
        float2 vf = __half22float2(vrow[c2]);
        qt[j * NH17 + n] = qf.x;
        qt[(j + 1) * NH17 + n] = qf.y;
        kt[j * NH17 + n] = kf.x;
        kt[(j + 1) * NH17 + n] = kf.y;
        vs[c] = vf.x;
        vs[c + 1] = vf.y;
    }
    __syncthreads();

    {
        int m = t >> 4;
        int n = t & 15;
        float acc = 0.0f;
        #pragma unroll 8
        for (int j = 0; j < DH; j++)
            acc += qt[j * NH17 + n] * kt[j * NH17 + m];
        w[n * NHEADS + m] = acc * (1.0f / 12.0f);
    }
    __syncthreads();

    if (t < NHEADS) {
        float mx = -1e30f;
        #pragma unroll
        for (int m = 0; m < NHEADS; m++) mx = fmaxf(mx, w[t * NHEADS + m]);
        float sum = 0.0f;
        #pragma unroll
        for (int m = 0; m < NHEADS; m++) {
            float e = expf(w[t * NHEADS + m] - mx);
            w[t * NHEADS + m] = e;
            sum += e;
        }
        float inv = 1.0f / sum;
        #pragma unroll
        for (int m = 0; m < NHEADS; m++) w[t * NHEADS + m] *= inv;
    }
    __syncthreads();

    __half* arow = g_attnh + (size_t)p * HID;
    for (int c = t; c < HID; c += 256) {
        int n = c / DH;
        int j = c - n * DH;
        float acc = 0.0f;
        #pragma unroll
        for (int m = 0; m < NHEADS; m++)
            acc += w[n * NHEADS + m] * vs[m * DH + j];
        arow[c] = __float2half_rn(acc);
    }
}

// ======================= residual + LayerNorm (single pass, fp16 in) ======
__device__ __forceinline__ void block_sum2(float& a, float& b, float* red) {
    #pragma unroll
    for (int o = 16; o > 0; o >>= 1) {
        a += __shfl_xor_sync(0xFFFFFFFFu, a, o);
        b += __shfl_xor_sync(0xFFFFFFFFu, b, o);
    }
    int warp = threadIdx.x >> 5, lane = threadIdx.x & 31;
    if (lane == 0) { red[warp] = a; red[8 + warp] = b; }
    __syncthreads();
    if (warp == 0) {
        float x = (lane < 8) ? red[lane] : 0.0f;
        float y = (lane < 8) ? red[8 + lane] : 0.0f;
        #pragma unroll
        for (int o = 4; o > 0; o >>= 1) {
            x += __shfl_xor_sync(0xFFFFFFFFu, x, o);
            y += __shfl_xor_sync(0xFFFFFFFFu, y, o);
        }
        if (lane == 0) { red[0] = x; red[1] = y; }
    }
    __syncthreads();
    a = red[0];
    b = red[1];
    __syncthreads();
}

__global__ __launch_bounds__(256)
void ln_kernel(const float* __restrict__ bo,
               const float* __restrict__ gamma, const float* __restrict__ beta,
               float* __restrict__ out) {
    __shared__ float ybuf[HID];
    __shared__ float red[16];

    int row = blockIdx.x;
    int t = threadIdx.x;
    const __half2* xr   = (const __half2*)(g_xh  + (size_t)row * HID);
    const __half2* orow = (const __half2*)(g_o16 + (size_t)row * HID);

    float s = 0.0f, ss = 0.0f;
    for (int c2 = t; c2 < HID / 2; c2 += 256) {
        int c = 2 * c2;
        float2 xf = __half22float2(xr[c2]);
        float2 of = __half22float2(orow[c2]);
        float y0 = xf.x + of.x + bo[c];
        float y1 = xf.y + of.y + bo[c + 1];
        ybuf[c] = y0;
        ybuf[c + 1] = y1;
        s += y0 + y1;
        ss += y0 * y0 + y1 * y1;
    }
    block_sum2(s, ss, red);
    float mu = s * (1.0f / (float)HID);
    float var = ss * (1.0f / (float)HID) - mu * mu;
    float rstd = rsqrtf(var + 1e-5f);

    float* orow_out = out + (size_t)row * HID;
    for (int c = t; c < HID; c += 256) {
        orow_out[c] = (ybuf[c] - mu) * rstd * gamma[c] + beta[c];
    }
}

// ---------------------------------------------------------------------------
extern "C" void kernel_launch(void* const* d_in, const int* in_sizes, int n_in,
                              void* d_out, int out_size) {
    const float* x  = (const float*)d_in[0];
    const float* wq = (const float*)d_in[1];
    const float* bq = (const float*)d_in[2];
    const float* wk = (const float*)d_in[3];
    const float* bk = (const float*)d_in[4];
    const float* wv = (const float*)d_in[5];
    const float* bv = (const float*)d_in[6];
    const float* wo = (const float*)d_in[7];
    const float* bo = (const float*)d_in[8];
    const float* g  = (const float*)d_in[9];
    const float* bl = (const float*)d_in[10];
    float* out = (float*)d_out;

    int M = in_sizes[0] / HID;   // b*s = 8192

    __half *o16, *xh, *attnh, *wqkvh, *woh;
    cudaGetSymbolAddress((void**)&o16,   g_o16);
    cudaGetSymbolAddress((void**)&xh,    g_xh);
    cudaGetSymbolAddress((void**)&attnh, g_attnh);
    cudaGetSymbolAddress((void**)&wqkvh, g_wqkvh);
    cudaGetSymbolAddress((void**)&woh,   g_woh);

    static int smem_set = 0;
    if (!smem_set) {
        cudaFuncSetAttribute(gemm_qkv_kernel,
                             cudaFuncAttributeMaxDynamicSharedMemorySize, GEMM_SMEM_BYTES);
        cudaFuncSetAttribute(gemm_wo_kernel,
                             cudaFuncAttributeMaxDynamicSharedMemorySize, GEMM_SMEM_BYTES);
        smem_set = 1;
    }

    build_omega_kernel<<<(HALF_D + 255) / 256, 256>>>();
    build_rope_kernel<<<(SLEN * HALF_D + 255) / 256, 256>>>();

    {
        int nx4 = (M * HID) / 4;
        int nw4 = (HID * HID) / 4;
        int total = nx4 + 4 * nw4;
        convert_all_kernel<<<(total + 255) / 256, 256>>>(x, wq, wk, wv, wo,
                                                         xh, wqkvh, woh,
                                                         nx4, nw4);
    }

    dim3 qkvgrid(3 * HID / BN, M / BM);   // 54 x 64
    gemm_qkv_kernel<<<qkvgrid, 128, GEMM_SMEM_BYTES>>>(xh, wqkvh, bq, bk, bv, M, HID);

    attention_kernel<<<M, 256>>>(M);

    dim3 wogrid(HID / BN, M / BM);        // 18 x 64
    gemm_wo_kernel<<<wogrid, 128, GEMM_SMEM_BYTES>>>(attnh, woh, o16, M, HID, HID);

    ln_kernel<<<M, 256>>>(bo, g, bl, out);

    (void)n_in; (void)out_size;
}

// round 17
// speedup vs baseline: 1.0974x; 1.0259x over previous
#include <cuda_runtime.h>
#include <cuda_fp16.h>
#include <math.h>
#include <cstdint>

#define HID    2304
#define HALF_D 1152
#define NHEADS 16
#define NH17   17
#define DH     144
#define SLEN   2048
#define MMAX   8192

// -------- scratch (static device globals; no runtime allocation) ----------
__device__ __half g_q16[(size_t)MMAX * HID];
__device__ __half g_k16[(size_t)MMAX * HID];
__device__ __half g_v16[(size_t)MMAX * HID];
__device__ __half g_o16[(size_t)MMAX * HID];     // fp16 wo-GEMM output
__device__ __half g_xh[(size_t)MMAX * HID];
__device__ __half g_attnh[(size_t)MMAX * HID];
__device__ __half g_wqkvh[(size_t)3 * HID * HID];   // packed [3*HID, HID]
__device__ __half g_woh[(size_t)HID * HID];
__device__ float  g_cos[SLEN * HALF_D];
__device__ float  g_sin[SLEN * HALF_D];
__device__ double g_omega[HALF_D];

// ---------------------------------------------------------------------------
// RoPE tables.
// ---------------------------------------------------------------------------
__global__ void build_omega_kernel() {
    int i = blockIdx.x * blockDim.x + threadIdx.x;
    if (i < HALF_D) {
        double scale = (2.0 * (double)i) / (double)HID;
        g_omega[i] = exp(-scale * log(10000.0));
    }
}

__global__ void build_rope_kernel() {
    int idx = blockIdx.x * blockDim.x + threadIdx.x;
    if (idx >= SLEN * HALF_D) return;
    int pos = idx / HALF_D;
    int i   = idx - pos * HALF_D;
    double ang = (double)pos * g_omega[i];
    double n = floor(ang * 0.15915494309189535);
    double r = ang - n * 6.283185307179586476925286766559;
    float s, c;
    sincosf((float)r, &s, &c);
    g_cos[idx] = c;
    g_sin[idx] = s;
}

// ---------------------------------------------------------------------------
// One-shot conversion, direct-indexed (one float4 per thread, one branch).
// ---------------------------------------------------------------------------
__global__ void convert_all_kernel(const float* __restrict__ x,
                                   const float* __restrict__ wq,
                                   const float* __restrict__ wk,
                                   const float* __restrict__ wv,
                                   const float* __restrict__ wo,
                                   __half* __restrict__ xh,
                                   __half* __restrict__ wqkvh,
                                   __half* __restrict__ woh,
                                   int nx4, int nw4) {
    int i = blockIdx.x * blockDim.x + threadIdx.x;
    int total = nx4 + 4 * nw4;
    if (i >= total) return;
    const float* src;
    __half* dst;
    int idx;
    if (i < nx4) {
        src = x; dst = xh; idx = i;
    } else {
        int j = i - nx4;
        int w = j / nw4;       // 0..3
        idx = j - w * nw4;
        src = (w == 0) ? wq : (w == 1) ? wk : (w == 2) ? wv : wo;
        dst = (w == 0) ? wqkvh
            : (w == 1) ? wqkvh + (size_t)HID * HID
            : (w == 2) ? wqkvh + (size_t)2 * HID * HID
            : woh;
    }
    float4 v = ((const float4*)src)[idx];
    ((__half2*)dst)[2 * idx]     = __floats2half2_rn(v.x, v.y);
    ((__half2*)dst)[2 * idx + 1] = __floats2half2_rn(v.z, v.w);
}

// ---------------------------------------------------------------------------
// PTX helpers
// ---------------------------------------------------------------------------
__device__ __forceinline__ void cp_async16(uint32_t dst, const void* src) {
    asm volatile("cp.async.cg.shared.global [%0], [%1], 16;\n" :: "r"(dst), "l"(src));
}
__device__ __forceinline__ void cp_commit() {
    asm volatile("cp.async.commit_group;\n");
}
__device__ __forceinline__ void cp_wait1() {
    asm volatile("cp.async.wait_group 1;\n");
}

#define LDSM4(r0, r1, r2, r3, addr) \
    asm volatile("ldmatrix.sync.aligned.m8n8.x4.shared.b16 {%0,%1,%2,%3}, [%4];" \
                 : "=r"(r0), "=r"(r1), "=r"(r2), "=r"(r3) : "r"(addr))

#define MMA_F16(d, a0, a1, a2, a3, b0, b1) \
    asm volatile("mma.sync.aligned.m16n8k16.row.col.f32.f16.f16.f32 " \
                 "{%0,%1,%2,%3}, {%4,%5,%6,%7}, {%8,%9}, {%0,%1,%2,%3};" \
                 : "+f"((d)[0]), "+f"((d)[1]), "+f"((d)[2]), "+f"((d)[3]) \
                 : "r"(a0), "r"(a1), "r"(a2), "r"(a3), "r"(b0), "r"(b1))

// ---------------------------------------------------------------------------
// GEMM core: CTA tile 128x128, 128 threads (4 warps, 64x64), 2 CTAs/SM,
// 3-stage cp.async pipeline + LDSM double-buffering (R13 schedule).
// ---------------------------------------------------------------------------
#define BM 128
#define BN 128
#define BKH 64                              // K halfs per stage (128 bytes)
#define A_BYTES (BM * 128)
#define B_BYTES (BN * 128)
#define STAGE_BYTES (A_BYTES + B_BYTES)     // 32768
#define GEMM_SMEM_BYTES (3 * STAGE_BYTES)   // 98304 per CTA

__device__ __forceinline__ void load_stage(const __half* __restrict__ A,
                                           const __half* __restrict__ B,
                                           int K, int bm, int bn, int k0,
                                           uint32_t stg, int tid) {
    #pragma unroll
    for (int i = 0; i < 8; i++) {
        int e = i * 128 + tid;
        int r = e >> 3;
        int cb = (e & 7) * 16;
        cp_async16(stg + r * 128 + (cb ^ ((r & 7) << 4)),
                   A + (size_t)(bm + r) * K + k0 + (e & 7) * 8);
    }
    #pragma unroll
    for (int i = 0; i < 8; i++) {
        int e = i * 128 + tid;
        int r = e >> 3;
        int cb = (e & 7) * 16;
        cp_async16(stg + A_BYTES + r * 128 + (cb ^ ((r & 7) << 4)),
                   B + (size_t)(bn + r) * K + k0 + (e & 7) * 8);
    }
}

struct Frag { uint32_t a[4][4]; uint32_t b[4][4]; };

__device__ __forceinline__ void ldsm_all(Frag& f, uint32_t stg, int kk,
                                         const int* rowA, const int* rowB,
                                         int lh, int lc) {
    const int kbL = kk * 32;
    #pragma unroll
    for (int mb = 0; mb < 4; mb++) {
        uint32_t ad = stg + rowA[mb] * 128 +
                      ((kbL + lc * 16) ^ ((rowA[mb] & 7) << 4));
        LDSM4(f.a[mb][0], f.a[mb][1], f.a[mb][2], f.a[mb][3], ad);
    }
    #pragma unroll
    for (int j = 0; j < 4; j++) {
        uint32_t bd = stg + A_BYTES + rowB[j] * 128 +
                      ((kbL + lh * 16) ^ ((rowB[j] & 7) << 4));
        LDSM4(f.b[j][0], f.b[j][1], f.b[j][2], f.b[j][3], bd);
    }
}

__device__ __forceinline__ void mma_all(float acc[4][8][4], const Frag& f) {
    #pragma unroll
    for (int mb = 0; mb < 4; mb++)
        #pragma unroll
        for (int j = 0; j < 4; j++) {
            MMA_F16(acc[mb][2 * j],     f.a[mb][0], f.a[mb][1], f.a[mb][2], f.a[mb][3],
                    f.b[j][0], f.b[j][1]);
            MMA_F16(acc[mb][2 * j + 1], f.a[mb][0], f.a[mb][1], f.a[mb][2], f.a[mb][3],
                    f.b[j][2], f.b[j][3]);
        }
}

__device__ __forceinline__ void gemm_mainloop(const __half* A, const __half* B,
                                              int K, int bm, int bn,
                                              uint32_t sbase, int tid,
                                              const int* rowA, const int* rowB,
                                              int lh, int lc,
                                              float acc[4][8][4]) {
    const int kIters = K / BKH;   // 36

    load_stage(A, B, K, bm, bn, 0, sbase, tid);
    cp_commit();
    load_stage(A, B, K, bm, bn, BKH, sbase + STAGE_BYTES, tid);
    cp_commit();

    int stage = 0;
    for (int kt = 0; kt < kIters; kt++) {
        cp_wait1();
        __syncthreads();

        int nk = kt + 2;
        if (nk < kIters)
            load_stage(A, B, K, bm, bn, nk * BKH,
                       sbase + (nk % 3) * STAGE_BYTES, tid);
        cp_commit();

        const uint32_t stg = sbase + stage * STAGE_BYTES;

        Frag f[2];
        ldsm_all(f[0], stg, 0, rowA, rowB, lh, lc);
        #pragma unroll
        for (int kk = 0; kk < 4; kk++) {
            int cur = kk & 1;
            if (kk < 3) ldsm_all(f[cur ^ 1], stg, kk + 1, rowA, rowB, lh, lc);
            mma_all(acc, f[cur]);
        }

        stage = (stage + 1 == 3) ? 0 : stage + 1;
    }
}

// ---------------------------------------------------------------------------
// Fused q/k/v projection: B packed [3*HID, HID]; per-CTA sel picks output.
// ---------------------------------------------------------------------------
__global__ __launch_bounds__(128, 2)
void gemm_qkv_kernel(const __half* __restrict__ A, const __half* __restrict__ B,
                     const float* __restrict__ bq, const float* __restrict__ bk,
                     const float* __restrict__ bv, int M, int K) {
    extern __shared__ char smem[];
    uint32_t sbase;
    asm("{ .reg .u64 t; cvta.to.shared.u64 t, %1; cvt.u32.u64 %0, t; }"
        : "=r"(sbase) : "l"(smem));

    const int tid  = threadIdx.x;
    const int warp = tid >> 5;
    const int lane = tid & 31;
    const int bm = blockIdx.y * BM;
    const int bn = blockIdx.x * BN;
    const int wm = (warp >> 1) * 64;
    const int wn = (warp & 1) * 64;

    const int lr = lane & 7;
    const int lh = (lane >> 3) & 1;
    const int lc = lane >> 4;

    int rowA[4], rowB[4];
    #pragma unroll
    for (int mb = 0; mb < 4; mb++) rowA[mb] = wm + mb * 16 + lr + lh * 8;
    #pragma unroll
    for (int j = 0; j < 4; j++)    rowB[j] = wn + j * 16 + lr + lc * 8;

    float acc[4][8][4];
    #pragma unroll
    for (int mb = 0; mb < 4; mb++)
        #pragma unroll
        for (int nb = 0; nb < 8; nb++)
            #pragma unroll
            for (int e = 0; e < 4; e++) acc[mb][nb][e] = 0.0f;

    gemm_mainloop(A, B, K, bm, bn, sbase, tid, rowA, rowB, lh, lc, acc);

    // ---- epilogue: per-CTA uniform output selection ----
    const int sel   = bn / HID;              // 0=q, 1=k, 2=v
    const int cbase = bn - sel * HID;
    const float* bias = (sel == 0) ? bq : (sel == 1) ? bk : bv;
    __half* Ch = (sel == 0) ? g_q16 : (sel == 1) ? g_k16 : g_v16;

    #pragma unroll
    for (int mb = 0; mb < 4; mb++) {
        const int r0 = bm + wm + mb * 16 + (lane >> 2);
        #pragma unroll
        for (int nb = 0; nb < 8; nb++) {
            const int lcol = cbase + wn + nb * 8 + (lane & 3) * 2;
            float x0 = acc[mb][nb][0], x1 = acc[mb][nb][1];
            float y0 = acc[mb][nb][2], y1 = acc[mb][nb][3];
            float2 bb = *(const float2*)(bias + lcol);
            x0 += bb.x; x1 += bb.y;
            y0 += bb.x; y1 += bb.y;
            if (sel < 2) {   // RoPE for q, k
                const int i = lcol >> 1;
                const int p0 = r0 & (SLEN - 1);
                const int p1 = (r0 + 8) & (SLEN - 1);
                float c0 = g_cos[p0 * HALF_D + i], s0 = g_sin[p0 * HALF_D + i];
                float c1 = g_cos[p1 * HALF_D + i], s1 = g_sin[p1 * HALF_D + i];
                float t0 = c0 * x0 - s0 * x1;
                float t1 = s0 * x0 + c0 * x1;
                x0 = t0; x1 = t1;
                t0 = c1 * y0 - s1 * y1;
                t1 = s1 * y0 + c1 * y1;
                y0 = t0; y1 = t1;
            }
            *(__half2*)(Ch + (size_t)r0 * HID + lcol)       = __floats2half2_rn(x0, x1);
            *(__half2*)(Ch + (size_t)(r0 + 8) * HID + lcol) = __floats2half2_rn(y0, y1);
        }
    }
}

// ---------------------------------------------------------------------------
// Output projection GEMM: fp16 store (feeds LN).
// ---------------------------------------------------------------------------
__global__ __launch_bounds__(128, 2)
void gemm_wo_kernel(const __half* __restrict__ A, const __half* __restrict__ B,
                    __half* __restrict__ C, int M, int N, int K) {
    extern __shared__ char smem[];
    uint32_t sbase;
    asm("{ .reg .u64 t; cvta.to.shared.u64 t, %1; cvt.u32.u64 %0, t; }"
        : "=r"(sbase) : "l"(smem));

    const int tid  = threadIdx.x;
    const int warp = tid >> 5;
    const int lane = tid & 31;
    const int bm = blockIdx.y * BM;
    const int bn = blockIdx.x * BN;
    const int wm = (warp >> 1) * 64;
    const int wn = (warp & 1) * 64;

    const int lr = lane & 7;
    const int lh = (lane >> 3) & 1;
    const int lc = lane >> 4;

    int rowA[4], rowB[4];
    #pragma unroll
    for (int mb = 0; mb < 4; mb++) rowA[mb] = wm + mb * 16 + lr + lh * 8;
    #pragma unroll
    for (int j = 0; j < 4; j++)    rowB[j] = wn + j * 16 + lr + lc * 8;

    float acc[4][8][4];
    #pragma unroll
    for (int mb = 0; mb < 4; mb++)
        #pragma unroll
        for (int nb = 0; nb < 8; nb++)
            #pragma unroll
            for (int e = 0; e < 4; e++) acc[mb][nb][e] = 0.0f;

    gemm_mainloop(A, B, K, bm, bn, sbase, tid, rowA, rowB, lh, lc, acc);

    #pragma unroll
    for (int mb = 0; mb < 4; mb++) {
        const int r0 = bm + wm + mb * 16 + (lane >> 2);
        #pragma unroll
        for (int nb = 0; nb < 8; nb++) {
            const int gc = bn + wn + nb * 8 + (lane & 3) * 2;
            *(__half2*)(C + (size_t)r0 * N + gc) =
                __floats2half2_rn(acc[mb][nb][0], acc[mb][nb][1]);
            *(__half2*)(C + (size_t)(r0 + 8) * N + gc) =
                __floats2half2_rn(acc[mb][nb][2], acc[mb][nb][3]);
        }
    }
}

// ======================= head-mixing attention =============================
// float2-packed smem along j (pairs never cross head boundary): halves LDS.
#define NJ2 (DH / 2)     // 72 j-pairs per head
__global__ __launch_bounds__(256)
void attention_kernel(int M) {
    __shared__ float2 qt2[NJ2 * NH17];   // [j2][n], stride 17
    __shared__ float2 kt2[NJ2 * NH17];   // [j2][m], stride 17
    __shared__ float  vs[HID];
    __shared__ float  w[NHEADS * NHEADS];

    int p = blockIdx.x;
    int t = threadIdx.x;
    const __half2* qrow = (const __half2*)(g_q16 + (size_t)p * HID);
    const __half2* krow = (const __half2*)(g_k16 + (size_t)p * HID);
    const __half2* vrow = (const __half2*)(g_v16 + (size_t)p * HID);

    for (int c2 = t; c2 < HID / 2; c2 += 256) {
        int c = 2 * c2;
        int n = c / DH;
        int j = c - n * DH;          // even; (j, j+1) stay in head n
        int j2 = j >> 1;
        float2 qf = __half22float2(qrow[c2]);
        float2 kf = __half22float2(krow[c2]);
        float2 vf = __half22float2(vrow[c2]);
        qt2[j2 * NH17 + n] = qf;
        kt2[j2 * NH17 + n] = kf;
        vs[c] = vf.x;
        vs[c + 1] = vf.y;
    }
    __syncthreads();

    {
        int m = t >> 4;
        int n = t & 15;
        float acc = 0.0f;
        #pragma unroll 8
        for (int j2 = 0; j2 < NJ2; j2++) {
            float2 a = qt2[j2 * NH17 + n];
            float2 b = kt2[j2 * NH17 + m];
            acc += a.x * b.x + a.y * b.y;
        }
        w[n * NHEADS + m] = acc * (1.0f / 12.0f);
    }
    __syncthreads();

    if (t < NHEADS) {
        float mx = -1e30f;
        #pragma unroll
        for (int m = 0; m < NHEADS; m++) mx = fmaxf(mx, w[t * NHEADS + m]);
        float sum = 0.0f;
        #pragma unroll
        for (int m = 0; m < NHEADS; m++) {
            float e = expf(w[t * NHEADS + m] - mx);
            w[t * NHEADS + m] = e;
            sum += e;
        }
        float inv = 1.0f / sum;
        #pragma unroll
        for (int m = 0; m < NHEADS; m++) w[t * NHEADS + m] *= inv;
    }
    __syncthreads();

    __half2* arow = (__half2*)(g_attnh + (size_t)p * HID);
    for (int c2 = t; c2 < HID / 2; c2 += 256) {
        int c = 2 * c2;
        int n = c / DH;
        int j = c - n * DH;          // even; pair stays within head
        float a0 = 0.0f, a1 = 0.0f;
        #pragma unroll
        for (int m = 0; m < NHEADS; m++) {
            float wm = w[n * NHEADS + m];
            float2 v2 = *(const float2*)&vs[m * DH + j];
            a0 += wm * v2.x;
            a1 += wm * v2.y;
        }
        arow[c2] = __floats2half2_rn(a0, a1);
    }
}

// ======================= residual + LayerNorm (single pass, fp16 in) ======
__device__ __forceinline__ void block_sum2(float& a, float& b, float* red) {
    #pragma unroll
    for (int o = 16; o > 0; o >>= 1) {
        a += __shfl_xor_sync(0xFFFFFFFFu, a, o);
        b += __shfl_xor_sync(0xFFFFFFFFu, b, o);
    }
    int warp = threadIdx.x >> 5, lane = threadIdx.x & 31;
    if (lane == 0) { red[warp] = a; red[8 + warp] = b; }
    __syncthreads();
    if (warp == 0) {
        float x = (lane < 8) ? red[lane] : 0.0f;
        float y = (lane < 8) ? red[8 + lane] : 0.0f;
        #pragma unroll
        for (int o = 4; o > 0; o >>= 1) {
            x += __shfl_xor_sync(0xFFFFFFFFu, x, o);
            y += __shfl_xor_sync(0xFFFFFFFFu, y, o);
        }
        if (lane == 0) { red[0] = x; red[1] = y; }
    }
    __syncthreads();
    a = red[0];
    b = red[1];
    __syncthreads();
}

__global__ __launch_bounds__(256)
void ln_kernel(const float* __restrict__ bo,
               const float* __restrict__ gamma, const float* __restrict__ beta,
               float* __restrict__ out) {
    __shared__ float ybuf[HID];
    __shared__ float red[16];

    int row = blockIdx.x;
    int t = threadIdx.x;
    const __half2* xr   = (const __half2*)(g_xh  + (size_t)row * HID);
    const __half2* orow = (const __half2*)(g_o16 + (size_t)row * HID);

    float s = 0.0f, ss = 0.0f;
    for (int c2 = t; c2 < HID / 2; c2 += 256) {
        int c = 2 * c2;
        float2 xf = __half22float2(xr[c2]);
        float2 of = __half22float2(orow[c2]);
        float y0 = xf.x + of.x + bo[c];
        float y1 = xf.y + of.y + bo[c + 1];
        ybuf[c] = y0;
        ybuf[c + 1] = y1;
        s += y0 + y1;
        ss += y0 * y0 + y1 * y1;
    }
    block_sum2(s, ss, red);
    float mu = s * (1.0f / (float)HID);
    float var = ss * (1.0f / (float)HID) - mu * mu;
    float rstd = rsqrtf(var + 1e-5f);

    float* orow_out = out + (size_t)row * HID;
    for (int c = t; c < HID; c += 256) {
        orow_out[c] = (ybuf[c] - mu) * rstd * gamma[c] + beta[c];
    }
}

// ---------------------------------------------------------------------------
extern "C" void kernel_launch(void* const* d_in, const int* in_sizes, int n_in,
                              void* d_out, int out_size) {
    const float* x  = (const float*)d_in[0];
    const float* wq = (const float*)d_in[1];
    const float* bq = (const float*)d_in[2];
    const float* wk = (const float*)d_in[3];
    const float* bk = (const float*)d_in[4];
    const float* wv = (const float*)d_in[5];
    const float* bv = (const float*)d_in[6];
    const float* wo = (const float*)d_in[7];
    const float* bo = (const float*)d_in[8];
    const float* g  = (const float*)d_in[9];
    const float* bl = (const float*)d_in[10];
    float* out = (float*)d_out;

    int M = in_sizes[0] / HID;   // b*s = 8192

    __half *o16, *xh, *attnh, *wqkvh, *woh;
    cudaGetSymbolAddress((void**)&o16,   g_o16);
    cudaGetSymbolAddress((void**)&xh,    g_xh);
    cudaGetSymbolAddress((void**)&attnh, g_attnh);
    cudaGetSymbolAddress((void**)&wqkvh, g_wqkvh);
    cudaGetSymbolAddress((void**)&woh,   g_woh);

    static int smem_set = 0;
    if (!smem_set) {
        cudaFuncSetAttribute(gemm_qkv_kernel,
                             cudaFuncAttributeMaxDynamicSharedMemorySize, GEMM_SMEM_BYTES);
        cudaFuncSetAttribute(gemm_wo_kernel,
                             cudaFuncAttributeMaxDynamicSharedMemorySize, GEMM_SMEM_BYTES);
        smem_set = 1;
    }

    build_omega_kernel<<<(HALF_D + 255) / 256, 256>>>();
    build_rope_kernel<<<(SLEN * HALF_D + 255) / 256, 256>>>();

    {
        int nx4 = (M * HID) / 4;
        int nw4 = (HID * HID) / 4;
        int total = nx4 + 4 * nw4;
        convert_all_kernel<<<(total + 255) / 256, 256>>>(x, wq, wk, wv, wo,
                                                         xh, wqkvh, woh,
                                                         nx4, nw4);
    }

    dim3 qkvgrid(3 * HID / BN, M / BM);   // 54 x 64
    gemm_qkv_kernel<<<qkvgrid, 128, GEMM_SMEM_BYTES>>>(xh, wqkvh, bq, bk, bv, M, HID);

    attention_kernel<<<M, 256>>>(M);

    dim3 wogrid(HID / BN, M / BM);        // 18 x 64
    gemm_wo_kernel<<<wogrid, 128, GEMM_SMEM_BYTES>>>(attnh, woh, o16, M, HID, HID);

    ln_kernel<<<M, 256>>>(bo, g, bl, out);

    (void)n_in; (void)out_size;
}